// round 4
// baseline (speedup 1.0000x reference)
#include <cuda_runtime.h>

#define V_TOTAL     8192
#define NODE_DIM    256
#define MAX_DEG     64
#define NUM_SAMPLES 16
#define GROUP_DIM   4
#define N_NODES     100000

#define BM 64
#define BN 128
#define BK 32
#define NCHUNK (NODE_DIM / BK)   // 8
#define AST (BK + 4)             // 36 floats: rows 16B-aligned, no read conflicts

// Scratch for linear-branch result L = features[ids] @ W + b   (8 MB)
__device__ float g_L[V_TOTAL * NODE_DIM];

// Packed fp32x2 FMA (Blackwell): d = a*b + d, two fp32 lanes per instruction.
#define FMA2(d, a, b) \
    asm("fma.rn.f32x2 %0, %1, %2, %0;" : "+l"(d) : "l"(a), "l"(b))

static __device__ __forceinline__ unsigned long long dup_f32(float x) {
    unsigned long long r;
    asm("mov.b64 %0, {%1, %1};" : "=l"(r) : "r"(__float_as_uint(x)));
    return r;
}
static __device__ __forceinline__ float2 unpack_f32x2(unsigned long long v) {
    float2 r;
    asm("mov.b64 {%0, %1}, %2;" : "=f"(r.x), "=f"(r.y) : "l"(v));
    return r;
}

// ---------------------------------------------------------------------------
// Kernel 1: L = features[ids] @ W + b   (M=8192, N=256, K=256, fp32)
// 64x128 block tile, 256 threads, 4x8 microtile (4 m scalars-dup'd x 4 packed
// n-pairs = 16 FFMA2 per thread per k). B tile [k][n] is n-contiguous, so one
// LDS.128 yields two packed f32x2 operands with zero pack cost. Smem traffic
// per k-iter (A 4 broadcast scalars + B 2 LDS.128 per warp) now matches the
// FMA-pipe time -> ~128 MAC/cyc/SM instead of smem-bound 64.
// Double-buffered, one __syncthreads per BK chunk.
// ---------------------------------------------------------------------------
__global__ void __launch_bounds__(256) linear_kernel(
    const int*   __restrict__ ids,
    const float* __restrict__ features,
    const float* __restrict__ W,
    const float* __restrict__ b)
{
    __shared__ float As[2][BM][AST];   // 18.4 KB
    __shared__ float Bs[2][BK][BN];    // 32 KB
    __shared__ int   rowid[BM];

    const int tid = threadIdx.x;
    const int tx  = tid & 15;          // n-dir: 16 threads * 8 cols
    const int ty  = tid >> 4;          // m-dir: 16 threads * 4 rows
    const int m0  = blockIdx.x * BM;
    const int n0  = blockIdx.y * BN;

    if (tid < BM) rowid[tid] = ids[m0 + tid];
    __syncthreads();

    // Fill decomposition. A: 2 float4/thread. B: 4 float4/thread.
    const int ar  = tid >> 3;          // A rows ar, ar+32
    const int ac  = (tid & 7) * 4;
    const int bkr = tid >> 5;          // B k-rows bkr, bkr+8, bkr+16, bkr+24
    const int bc  = (tid & 31) * 4;

    const size_t rowA0 = (size_t)rowid[ar]      * NODE_DIM;
    const size_t rowA1 = (size_t)rowid[ar + 32] * NODE_DIM;
    const float* Wb = W + n0 + bc;

    unsigned long long acc[4][4];
#pragma unroll
    for (int i = 0; i < 4; i++)
#pragma unroll
        for (int j = 0; j < 4; j++) acc[i][j] = 0ull;

    // Prefetch + store chunk 0.
    float4 pa0 = *(const float4*)&features[rowA0 + ac];
    float4 pa1 = *(const float4*)&features[rowA1 + ac];
    float4 pb[4];
#pragma unroll
    for (int j = 0; j < 4; j++)
        pb[j] = *(const float4*)&Wb[(size_t)(bkr + 8 * j) * NODE_DIM];
    *(float4*)&As[0][ar     ][ac] = pa0;
    *(float4*)&As[0][ar + 32][ac] = pa1;
#pragma unroll
    for (int j = 0; j < 4; j++)
        *(float4*)&Bs[0][bkr + 8 * j][bc] = pb[j];
    __syncthreads();

    int buf = 0;
#pragma unroll
    for (int c = 0; c < NCHUNK; c++) {
        if (c + 1 < NCHUNK) {
            const int kc = (c + 1) * BK;
            pa0 = *(const float4*)&features[rowA0 + kc + ac];
            pa1 = *(const float4*)&features[rowA1 + kc + ac];
#pragma unroll
            for (int j = 0; j < 4; j++)
                pb[j] = *(const float4*)&Wb[(size_t)(kc + bkr + 8 * j) * NODE_DIM];
        }

#pragma unroll
        for (int k = 0; k < BK; k++) {
            const unsigned long long a0 = dup_f32(As[buf][ty * 4 + 0][k]);
            const unsigned long long a1 = dup_f32(As[buf][ty * 4 + 1][k]);
            const unsigned long long a2 = dup_f32(As[buf][ty * 4 + 2][k]);
            const unsigned long long a3 = dup_f32(As[buf][ty * 4 + 3][k]);
            const ulonglong2 b01 = *(const ulonglong2*)&Bs[buf][k][tx * 8];
            const ulonglong2 b23 = *(const ulonglong2*)&Bs[buf][k][tx * 8 + 4];

            FMA2(acc[0][0], a0, b01.x); FMA2(acc[0][1], a0, b01.y);
            FMA2(acc[0][2], a0, b23.x); FMA2(acc[0][3], a0, b23.y);
            FMA2(acc[1][0], a1, b01.x); FMA2(acc[1][1], a1, b01.y);
            FMA2(acc[1][2], a1, b23.x); FMA2(acc[1][3], a1, b23.y);
            FMA2(acc[2][0], a2, b01.x); FMA2(acc[2][1], a2, b01.y);
            FMA2(acc[2][2], a2, b23.x); FMA2(acc[2][3], a2, b23.y);
            FMA2(acc[3][0], a3, b01.x); FMA2(acc[3][1], a3, b01.y);
            FMA2(acc[3][2], a3, b23.x); FMA2(acc[3][3], a3, b23.y);
        }

        if (c + 1 < NCHUNK) {
            *(float4*)&As[buf ^ 1][ar     ][ac] = pa0;
            *(float4*)&As[buf ^ 1][ar + 32][ac] = pa1;
#pragma unroll
            for (int j = 0; j < 4; j++)
                *(float4*)&Bs[buf ^ 1][bkr + 8 * j][bc] = pb[j];
        }
        __syncthreads();
        buf ^= 1;
    }

    const float4 bias0 = *(const float4*)&b[n0 + tx * 8];
    const float4 bias1 = *(const float4*)&b[n0 + tx * 8 + 4];
#pragma unroll
    for (int i = 0; i < 4; i++) {
        const float2 p0 = unpack_f32x2(acc[i][0]);
        const float2 p1 = unpack_f32x2(acc[i][1]);
        const float2 p2 = unpack_f32x2(acc[i][2]);
        const float2 p3 = unpack_f32x2(acc[i][3]);
        float4 o0, o1;
        o0.x = p0.x + bias0.x;  o0.y = p0.y + bias0.y;
        o0.z = p1.x + bias0.z;  o0.w = p1.y + bias0.w;
        o1.x = p2.x + bias1.x;  o1.y = p2.y + bias1.y;
        o1.z = p3.x + bias1.z;  o1.w = p3.y + bias1.w;
        const int m = m0 + ty * 4 + i;
        *(float4*)&g_L[(size_t)m * NODE_DIM + n0 + tx * 8]     = o0;
        *(float4*)&g_L[(size_t)m * NODE_DIM + n0 + tx * 8 + 4] = o1;
    }
}

// ---------------------------------------------------------------------------
// Kernel 2: per-v neighbor scoring + grouped argmin + outputs (R1 version:
// 32 regs, 92% occ — near its L2-gather throughput wall).
//
// Output layout (float32):
//   [0,            131072)  sel  (node ids, exact in fp32)
//   [131072,       262144)  att  (all 1.0)
//   [262144,       270336)  numnz
//   [270336,       278528)  numnz (duplicate)
// ---------------------------------------------------------------------------
__global__ void __launch_bounds__(256) sampler_kernel(
    const int*   __restrict__ ids,
    const int*   __restrict__ adj,
    const float* __restrict__ features,
    float*       __restrict__ out)
{
    __shared__ float ls[NODE_DIM];
    __shared__ float scores[MAX_DEG];
    __shared__ int   nbr[MAX_DEG];
    __shared__ float flags[NUM_SAMPLES];

    const int v    = blockIdx.x;
    const int tid  = threadIdx.x;
    const int lane = tid & 31;
    const int w    = tid >> 5;

    const int vid = __ldg(&ids[v]);

    ls[tid] = g_L[(size_t)v * NODE_DIM + tid];
    if (tid < MAX_DEG) nbr[tid] = adj[(size_t)vid * MAX_DEG + tid];
    __syncthreads();

    const float4 lv0 = ((const float4*)ls)[lane];
    const float4 lv1 = ((const float4*)ls)[lane + 32];

#pragma unroll
    for (int t = 0; t < 8; t++) {
        const int k  = w * 8 + t;
        const int nb = nbr[k];
        const float4* fr = (const float4*)(features + (size_t)nb * NODE_DIM);
        const float4 f0 = __ldg(&fr[lane]);
        const float4 f1 = __ldg(&fr[lane + 32]);

        float s = f0.x * lv0.x + f0.y * lv0.y + f0.z * lv0.z + f0.w * lv0.w
                + f1.x * lv1.x + f1.y * lv1.y + f1.z * lv1.z + f1.w * lv1.w;

#pragma unroll
        for (int off = 16; off > 0; off >>= 1)
            s += __shfl_xor_sync(0xffffffffu, s, off);

        if (lane == 0) scores[k] = fmaxf(s, 0.0f);
    }
    __syncthreads();

    if (tid < NUM_SAMPLES) {
        const int base = tid * GROUP_DIM;
        float m  = scores[base];
        int   bi = 0;
#pragma unroll
        for (int g = 1; g < GROUP_DIM; g++) {
            float sc = scores[base + g];
            if (sc < m) { m = sc; bi = g; }       // strict <  => first min
        }
        const int sid = nbr[base + bi];
        out[(size_t)v * NUM_SAMPLES + tid]                          = (float)sid;
        out[(size_t)V_TOTAL * NUM_SAMPLES + v * NUM_SAMPLES + tid]  = 1.0f;
        flags[tid] = (sid == N_NODES - 1) ? 0.0f : 1.0f;
    }
    __syncthreads();

    if (tid == 0) {
        float nn = 0.0f;
#pragma unroll
        for (int s = 0; s < NUM_SAMPLES; s++) nn += flags[s];
        out[2 * V_TOTAL * NUM_SAMPLES + v]           = nn;
        out[2 * V_TOTAL * NUM_SAMPLES + V_TOTAL + v] = nn;
    }
}

extern "C" void kernel_launch(void* const* d_in, const int* in_sizes, int n_in,
                              void* d_out, int out_size)
{
    const int*   ids      = (const int*)  d_in[0];
    const int*   adj      = (const int*)  d_in[1];
    const float* features = (const float*)d_in[2];
    const float* W        = (const float*)d_in[3];
    const float* b        = (const float*)d_in[4];
    float*       out      = (float*)d_out;

    linear_kernel<<<dim3(V_TOTAL / BM, NODE_DIM / BN), 256>>>(ids, features, W, b);
    sampler_kernel<<<V_TOTAL, 256>>>(ids, adj, features, out);
}

// round 5
// speedup vs baseline: 1.2161x; 1.2161x over previous
#include <cuda_runtime.h>

#define V_TOTAL     8192
#define NODE_DIM    256
#define MAX_DEG     64
#define NUM_SAMPLES 16
#define GROUP_DIM   4
#define N_NODES     100000

#define BM 64
#define BN 128
#define BK 32
#define NCHUNK (NODE_DIM / BK)   // 8
#define AST (BK + 4)             // 36 floats: rows 16B-aligned, no read conflicts

// Scratch for linear-branch result L = features[ids] @ W + b   (8 MB)
__device__ float g_L[V_TOTAL * NODE_DIM];

// Packed fp32x2 FMA (Blackwell): d = a*b + d, two fp32 lanes per instruction.
#define FMA2(d, a, b) \
    asm("fma.rn.f32x2 %0, %1, %2, %0;" : "+l"(d) : "l"(a), "l"(b))

static __device__ __forceinline__ unsigned long long dup_f32(float x) {
    unsigned long long r;
    asm("mov.b64 %0, {%1, %1};" : "=l"(r) : "r"(__float_as_uint(x)));
    return r;
}
static __device__ __forceinline__ float2 unpack_f32x2(unsigned long long v) {
    float2 r;
    asm("mov.b64 {%0, %1}, %2;" : "=f"(r.x), "=f"(r.y) : "l"(v));
    return r;
}

// ---------------------------------------------------------------------------
// Kernel 1: L = features[ids] @ W + b   (M=8192, N=256, K=256, fp32)
// 64x128 block tile, 256 threads, 4x8 microtile. Each thread's 8 output
// columns are TWO float4 groups 64 apart (tx*4 and 64+tx*4): the resulting
// LDS.128 phase addresses are tx*16B, covering all 32 banks exactly once
// (conflict-free), unlike the tx*8 contiguous mapping which put every thread
// on the same bank quad (R3 regression). B values dup across half-warps ->
// broadcast. Double-buffered, one __syncthreads per BK chunk.
// ---------------------------------------------------------------------------
__global__ void __launch_bounds__(256) linear_kernel(
    const int*   __restrict__ ids,
    const float* __restrict__ features,
    const float* __restrict__ W,
    const float* __restrict__ b)
{
    __shared__ float As[2][BM][AST];   // 18.4 KB
    __shared__ float Bs[2][BK][BN];    // 32 KB
    __shared__ int   rowid[BM];

    const int tid = threadIdx.x;
    const int tx  = tid & 15;          // n-dir: cols tx*4..+3 and 64+tx*4..+3
    const int ty  = tid >> 4;          // m-dir: 16 threads * 4 rows
    const int m0  = blockIdx.x * BM;
    const int n0  = blockIdx.y * BN;

    if (tid < BM) rowid[tid] = ids[m0 + tid];
    __syncthreads();

    // Fill decomposition. A: 2 float4/thread. B: 4 float4/thread.
    const int ar  = tid >> 3;          // A rows ar, ar+32
    const int ac  = (tid & 7) * 4;
    const int bkr = tid >> 5;          // B k-rows bkr, bkr+8, bkr+16, bkr+24
    const int bc  = (tid & 31) * 4;

    const size_t rowA0 = (size_t)rowid[ar]      * NODE_DIM;
    const size_t rowA1 = (size_t)rowid[ar + 32] * NODE_DIM;
    const float* Wb = W + n0 + bc;

    unsigned long long acc[4][4];
#pragma unroll
    for (int i = 0; i < 4; i++)
#pragma unroll
        for (int j = 0; j < 4; j++) acc[i][j] = 0ull;

    // Prefetch + store chunk 0.
    float4 pa0 = *(const float4*)&features[rowA0 + ac];
    float4 pa1 = *(const float4*)&features[rowA1 + ac];
    float4 pb[4];
#pragma unroll
    for (int j = 0; j < 4; j++)
        pb[j] = *(const float4*)&Wb[(size_t)(bkr + 8 * j) * NODE_DIM];
    *(float4*)&As[0][ar     ][ac] = pa0;
    *(float4*)&As[0][ar + 32][ac] = pa1;
#pragma unroll
    for (int j = 0; j < 4; j++)
        *(float4*)&Bs[0][bkr + 8 * j][bc] = pb[j];
    __syncthreads();

    int buf = 0;
#pragma unroll
    for (int c = 0; c < NCHUNK; c++) {
        if (c + 1 < NCHUNK) {
            const int kc = (c + 1) * BK;
            pa0 = *(const float4*)&features[rowA0 + kc + ac];
            pa1 = *(const float4*)&features[rowA1 + kc + ac];
#pragma unroll
            for (int j = 0; j < 4; j++)
                pb[j] = *(const float4*)&Wb[(size_t)(kc + bkr + 8 * j) * NODE_DIM];
        }

#pragma unroll
        for (int k = 0; k < BK; k++) {
            const unsigned long long a0 = dup_f32(As[buf][ty * 4 + 0][k]);
            const unsigned long long a1 = dup_f32(As[buf][ty * 4 + 1][k]);
            const unsigned long long a2 = dup_f32(As[buf][ty * 4 + 2][k]);
            const unsigned long long a3 = dup_f32(As[buf][ty * 4 + 3][k]);
            // Conflict-free: phase addresses tx*16B hit each bank once.
            const ulonglong2 b01 = *(const ulonglong2*)&Bs[buf][k][tx * 4];
            const ulonglong2 b23 = *(const ulonglong2*)&Bs[buf][k][64 + tx * 4];

            FMA2(acc[0][0], a0, b01.x); FMA2(acc[0][1], a0, b01.y);
            FMA2(acc[0][2], a0, b23.x); FMA2(acc[0][3], a0, b23.y);
            FMA2(acc[1][0], a1, b01.x); FMA2(acc[1][1], a1, b01.y);
            FMA2(acc[1][2], a1, b23.x); FMA2(acc[1][3], a1, b23.y);
            FMA2(acc[2][0], a2, b01.x); FMA2(acc[2][1], a2, b01.y);
            FMA2(acc[2][2], a2, b23.x); FMA2(acc[2][3], a2, b23.y);
            FMA2(acc[3][0], a3, b01.x); FMA2(acc[3][1], a3, b01.y);
            FMA2(acc[3][2], a3, b23.x); FMA2(acc[3][3], a3, b23.y);
        }

        if (c + 1 < NCHUNK) {
            *(float4*)&As[buf ^ 1][ar     ][ac] = pa0;
            *(float4*)&As[buf ^ 1][ar + 32][ac] = pa1;
#pragma unroll
            for (int j = 0; j < 4; j++)
                *(float4*)&Bs[buf ^ 1][bkr + 8 * j][bc] = pb[j];
        }
        __syncthreads();
        buf ^= 1;
    }

    const float4 bias0 = *(const float4*)&b[n0 + tx * 4];
    const float4 bias1 = *(const float4*)&b[n0 + 64 + tx * 4];
#pragma unroll
    for (int i = 0; i < 4; i++) {
        const float2 p0 = unpack_f32x2(acc[i][0]);
        const float2 p1 = unpack_f32x2(acc[i][1]);
        const float2 p2 = unpack_f32x2(acc[i][2]);
        const float2 p3 = unpack_f32x2(acc[i][3]);
        float4 o0, o1;
        o0.x = p0.x + bias0.x;  o0.y = p0.y + bias0.y;
        o0.z = p1.x + bias0.z;  o0.w = p1.y + bias0.w;
        o1.x = p2.x + bias1.x;  o1.y = p2.y + bias1.y;
        o1.z = p3.x + bias1.z;  o1.w = p3.y + bias1.w;
        const int m = m0 + ty * 4 + i;
        *(float4*)&g_L[(size_t)m * NODE_DIM + n0 + tx * 4]      = o0;
        *(float4*)&g_L[(size_t)m * NODE_DIM + n0 + 64 + tx * 4] = o1;
    }
}

// ---------------------------------------------------------------------------
// Kernel 2: per-v neighbor scoring + grouped argmin + outputs (R1 version:
// 32 regs, ~94% occ — at the aggregate L2/DRAM gather wall).
//
// Output layout (float32):
//   [0,            131072)  sel  (node ids, exact in fp32)
//   [131072,       262144)  att  (all 1.0)
//   [262144,       270336)  numnz
//   [270336,       278528)  numnz (duplicate)
// ---------------------------------------------------------------------------
__global__ void __launch_bounds__(256) sampler_kernel(
    const int*   __restrict__ ids,
    const int*   __restrict__ adj,
    const float* __restrict__ features,
    float*       __restrict__ out)
{
    __shared__ float ls[NODE_DIM];
    __shared__ float scores[MAX_DEG];
    __shared__ int   nbr[MAX_DEG];
    __shared__ float flags[NUM_SAMPLES];

    const int v    = blockIdx.x;
    const int tid  = threadIdx.x;
    const int lane = tid & 31;
    const int w    = tid >> 5;

    const int vid = __ldg(&ids[v]);

    ls[tid] = g_L[(size_t)v * NODE_DIM + tid];
    if (tid < MAX_DEG) nbr[tid] = adj[(size_t)vid * MAX_DEG + tid];
    __syncthreads();

    const float4 lv0 = ((const float4*)ls)[lane];
    const float4 lv1 = ((const float4*)ls)[lane + 32];

#pragma unroll
    for (int t = 0; t < 8; t++) {
        const int k  = w * 8 + t;
        const int nb = nbr[k];
        const float4* fr = (const float4*)(features + (size_t)nb * NODE_DIM);
        const float4 f0 = __ldg(&fr[lane]);
        const float4 f1 = __ldg(&fr[lane + 32]);

        float s = f0.x * lv0.x + f0.y * lv0.y + f0.z * lv0.z + f0.w * lv0.w
                + f1.x * lv1.x + f1.y * lv1.y + f1.z * lv1.z + f1.w * lv1.w;

#pragma unroll
        for (int off = 16; off > 0; off >>= 1)
            s += __shfl_xor_sync(0xffffffffu, s, off);

        if (lane == 0) scores[k] = fmaxf(s, 0.0f);
    }
    __syncthreads();

    if (tid < NUM_SAMPLES) {
        const int base = tid * GROUP_DIM;
        float m  = scores[base];
        int   bi = 0;
#pragma unroll
        for (int g = 1; g < GROUP_DIM; g++) {
            float sc = scores[base + g];
            if (sc < m) { m = sc; bi = g; }       // strict <  => first min
        }
        const int sid = nbr[base + bi];
        out[(size_t)v * NUM_SAMPLES + tid]                          = (float)sid;
        out[(size_t)V_TOTAL * NUM_SAMPLES + v * NUM_SAMPLES + tid]  = 1.0f;
        flags[tid] = (sid == N_NODES - 1) ? 0.0f : 1.0f;
    }
    __syncthreads();

    if (tid == 0) {
        float nn = 0.0f;
#pragma unroll
        for (int s = 0; s < NUM_SAMPLES; s++) nn += flags[s];
        out[2 * V_TOTAL * NUM_SAMPLES + v]           = nn;
        out[2 * V_TOTAL * NUM_SAMPLES + V_TOTAL + v] = nn;
    }
}

extern "C" void kernel_launch(void* const* d_in, const int* in_sizes, int n_in,
                              void* d_out, int out_size)
{
    const int*   ids      = (const int*)  d_in[0];
    const int*   adj      = (const int*)  d_in[1];
    const float* features = (const float*)d_in[2];
    const float* W        = (const float*)d_in[3];
    const float* b        = (const float*)d_in[4];
    float*       out      = (float*)d_out;

    linear_kernel<<<dim3(V_TOTAL / BM, NODE_DIM / BN), 256>>>(ids, features, W, b);
    sampler_kernel<<<V_TOTAL, 256>>>(ids, adj, features, out);
}